// round 4
// baseline (speedup 1.0000x reference)
#include <cuda_runtime.h>
#include <cstdint>

// Gini of n=8192 fp32 vector, single fused launch.
//
// sum_{i,j}|xi-xj| is shift-invariant => the min-shift only affects mu.
// 16x16 triangular tiling (136 tiles of 512x512, off-diag weighted 2x),
// each tile split into 4 column strips of 128 => 544 uniform blocks
// (~3.7 blocks/SM => 32 warps/SM, covers the f32x2 add latency chains).
// Block 0 runs the min+sum pass concurrently. Last-done block finalizes.
//
// Per 2 packed columns: add.rn.f32x2 with negated column (diff, fma pipe),
// 64-bit AND sign-mask for abs (alu pipe), packed accumulate (fma pipe).

#define T_CHUNKS 16
#define CHUNK    512
#define STRIPS   4
#define SCOLS    (CHUNK / STRIPS)                 // 128
#define NTILES   (T_CHUNKS * (T_CHUNKS + 1) / 2)  // 136
#define NPAIRBLK (NTILES * STRIPS)                // 544
#define THREADS  256
#define GEN_MAX  4096

__device__ float        g_part[NPAIRBLK > GEN_MAX ? NPAIRBLK : GEN_MAX];
__device__ float        g_min_val;
__device__ float        g_sum_val;
__device__ unsigned int g_count = 0;

__device__ __forceinline__ uint64_t pack2(float lo, float hi) {
    uint64_t r;
    asm("mov.b64 %0, {%1, %2};" : "=l"(r) : "f"(lo), "f"(hi));
    return r;
}
__device__ __forceinline__ uint64_t addf32x2(uint64_t a, uint64_t b) {
    uint64_t r;
    asm("add.rn.f32x2 %0, %1, %2;" : "=l"(r) : "l"(a), "l"(b));
    return r;
}
__device__ __forceinline__ float unpack_sum(uint64_t a) {
    float lo, hi;
    asm("mov.b64 {%0, %1}, %2;" : "=f"(lo), "=f"(hi) : "l"(a));
    return lo + hi;
}

// fixed-order reduce of nblk partials + closed-form output; resets counter
__device__ __forceinline__ void finalize_last(int n, float* __restrict__ out,
                                              int nblk, float* red) {
    const int tid = threadIdx.x;
    float s = 0.0f;
    for (int i = tid; i < nblk; i += THREADS) s += g_part[i];
    red[tid] = s;
    __syncthreads();
    for (int off = THREADS / 2; off > 0; off >>= 1) {
        if (tid < off) red[tid] += red[tid + off];
        __syncthreads();
    }
    if (tid == 0) {
        const float nf = (float)n;
        float mean = g_sum_val / nf;
        float mn = g_min_val;
        if (mn < 0.0f) mean -= mn;                 // mean(x - min)
        out[0] = red[0] / (2.0f * nf * nf * (mean + 1e-8f));
        g_count = 0;                               // reset for graph replay
    }
}

// ---------------- fused kernel (n == 8192 path) ----------------
__global__ __launch_bounds__(THREADS)
void k_gini(const float* __restrict__ x, float* __restrict__ out, int n) {
    __shared__ float4 shv[SCOLS / 4];              // negated column strip (512 B)
    __shared__ float  red[THREADS];
    __shared__ unsigned int isLast;

    const int tid = threadIdx.x;
    const int b   = blockIdx.x;

    if (b == 0) {
        // -------- min + sum block (overlaps with pairwise blocks) --------
        __shared__ float smin[THREADS];
        float mn = 3.402823466e38f, sm = 0.0f;
        for (int i = tid; i < n; i += THREADS) {
            float v = x[i];
            mn = fminf(mn, v);
            sm += v;
        }
        red[tid] = sm;
        smin[tid] = mn;
        __syncthreads();
        for (int off = THREADS / 2; off > 0; off >>= 1) {
            if (tid < off) {
                red[tid] += red[tid + off];
                smin[tid] = fminf(smin[tid], smin[tid + off]);
            }
            __syncthreads();
        }
        if (tid == 0) {
            g_min_val = smin[0];
            g_sum_val = red[0];
            __threadfence();
            unsigned int c = atomicAdd(&g_count, 1u);
            isLast = (c == gridDim.x - 1) ? 1u : 0u;
        }
        __syncthreads();
        if (isLast) { __threadfence(); finalize_last(n, out, NPAIRBLK, red); }
        return;
    }

    // -------- pairwise tile strip --------
    const int t     = b - 1;
    const int strip = t & (STRIPS - 1);
    int rc = 0, rem = t >> 2;                      // tile index -> (rc, cc), rc <= cc
    while (rem >= T_CHUNKS - rc) { rem -= (T_CHUNKS - rc); rc++; }
    const int cc = rc + rem;
    const int colBase = cc * CHUNK + strip * SCOLS;
    const int rowBase = rc * CHUNK;

    // negated column strip into smem (32 threads x float4)
    if (tid < SCOLS / 4) {
        float4 v = reinterpret_cast<const float4*>(x + colBase)[tid];
        shv[tid] = make_float4(-v.x, -v.y, -v.z, -v.w);
    }
    const float r0 = x[rowBase + tid];
    const float r1 = x[rowBase + THREADS + tid];
    const uint64_t rp0 = pack2(r0, r0);
    const uint64_t rp1 = pack2(r1, r1);
    __syncthreads();

    const uint64_t MASK = 0x7FFFFFFF7FFFFFFFULL;
    uint64_t a0x = 0, a0y = 0, a1x = 0, a1y = 0;
    const ulonglong2* shq = reinterpret_cast<const ulonglong2*>(shv);

#pragma unroll 16
    for (int j = 0; j < SCOLS / 4; ++j) {          // 32 iters, 4 cols each
        const ulonglong2 c = shq[j];               // LDS.128 broadcast
        uint64_t d;
        d = addf32x2(rp0, c.x) & MASK;  a0x = addf32x2(a0x, d);
        d = addf32x2(rp0, c.y) & MASK;  a0y = addf32x2(a0y, d);
        d = addf32x2(rp1, c.x) & MASK;  a1x = addf32x2(a1x, d);
        d = addf32x2(rp1, c.y) & MASK;  a1y = addf32x2(a1y, d);
    }

    float mysum = unpack_sum(addf32x2(a0x, a0y)) + unpack_sum(addf32x2(a1x, a1y));

    red[tid] = mysum;
    __syncthreads();
    for (int off = THREADS / 2; off > 0; off >>= 1) {
        if (tid < off) red[tid] += red[tid + off];
        __syncthreads();
    }
    if (tid == 0) {
        float p = red[0];
        if (rc != cc) p *= 2.0f;                   // symmetry weight
        g_part[t] = p;
        __threadfence();
        unsigned int c = atomicAdd(&g_count, 1u);
        isLast = (c == gridDim.x - 1) ? 1u : 0u;
    }
    __syncthreads();
    if (isLast) { __threadfence(); finalize_last(n, out, NPAIRBLK, red); }
}

// ---------------- generic fallback (any n) ----------------
__global__ void k_gini_generic(const float* __restrict__ x, float* __restrict__ out, int n) {
    __shared__ float red[THREADS];
    __shared__ float smin[THREADS];
    __shared__ unsigned int isLast;
    const int tid = threadIdx.x;
    const int i = blockIdx.x * THREADS + tid;
    float a = 0.0f;
    if (i < n) {
        const float xi = x[i];
        for (int j = 0; j < n; ++j) a += fabsf(xi - x[j]);
    }
    red[tid] = a;
    __syncthreads();
    for (int off = THREADS / 2; off > 0; off >>= 1) {
        if (tid < off) red[tid] += red[tid + off];
        __syncthreads();
    }
    if (tid == 0) {
        g_part[blockIdx.x] = red[0];
        __threadfence();
        unsigned int c = atomicAdd(&g_count, 1u);
        isLast = (c == gridDim.x - 1) ? 1u : 0u;
    }
    __syncthreads();
    if (isLast) {
        __threadfence();
        // min/sum inline (generic path: no dedicated block)
        float mn = 3.402823466e38f, sm = 0.0f;
        for (int k = tid; k < n; k += THREADS) {
            float v = x[k];
            mn = fminf(mn, v);
            sm += v;
        }
        red[tid] = sm; smin[tid] = mn;
        __syncthreads();
        for (int off = THREADS / 2; off > 0; off >>= 1) {
            if (tid < off) {
                red[tid] += red[tid + off];
                smin[tid] = fminf(smin[tid], smin[tid + off]);
            }
            __syncthreads();
        }
        if (tid == 0) { g_min_val = smin[0]; g_sum_val = red[0]; }
        __syncthreads();
        // reduce partials
        float s = 0.0f;
        for (int k = tid; k < gridDim.x; k += THREADS) s += g_part[k];
        red[tid] = s;
        __syncthreads();
        for (int off = THREADS / 2; off > 0; off >>= 1) {
            if (tid < off) red[tid] += red[tid + off];
            __syncthreads();
        }
        if (tid == 0) {
            const float nf = (float)n;
            float mean = g_sum_val / nf;
            if (g_min_val < 0.0f) mean -= g_min_val;
            out[0] = red[0] / (2.0f * nf * nf * (mean + 1e-8f));
            g_count = 0;
        }
    }
}

extern "C" void kernel_launch(void* const* d_in, const int* in_sizes, int n_in,
                              void* d_out, int out_size) {
    const float* x = (const float*)d_in[0];
    float* out = (float*)d_out;
    const int n = in_sizes[0];

    if (n == T_CHUNKS * CHUNK) {
        k_gini<<<NPAIRBLK + 1, THREADS>>>(x, out, n);
    } else {
        int nblk = (n + THREADS - 1) / THREADS;
        if (nblk > GEN_MAX) nblk = GEN_MAX;
        k_gini_generic<<<nblk, THREADS>>>(x, out, n);
    }
}